// round 14
// baseline (speedup 1.0000x reference)
#include <cuda_runtime.h>
#include <cuda_fp16.h>
#include <cstdint>
#include <math.h>

#define BB 8
#define TT 2048
#define CC 1024
#define MM (BB * TT)   // 16384 rows

// ---------------- scratch (uint4-backed => guaranteed 16B alignment) ---------
// Referenced ONLY from device code (never passed from host).
__device__ uint4 g_xh4[(size_t)MM * CC / 8];          // fp16 x hi
__device__ uint4 g_wh4[(size_t)2 * CC * CC / 8];      // fp16 W hi
__device__ uint4 g_wl4[(size_t)2 * CC * CC / 8];      // fp16 W lo
__device__ uint4 g_qh4[(size_t)MM * CC / 8];          // fp16 q hi
__device__ uint4 g_kh4[(size_t)MM * CC / 8];          // fp16 k hi
__device__ uint4 g_kl4[(size_t)MM * CC / 8];          // fp16 k lo
__device__ float g_vw[MM];
__device__ float g_part[64 * CC];        // fold partials (fully overwritten)
__device__ float g_weff[CC];
__device__ float g_u[CC];
__device__ float g_scal[2];              // [0]=c0, [1]=const_out

#define G_XH ((__half*)g_xh4)
#define G_WH ((__half*)g_wh4)
#define G_WL ((__half*)g_wl4)
#define G_QH ((__half*)g_qh4)
#define G_KH ((__half*)g_kh4)
#define G_KL ((__half*)g_kl4)

// ================= base-ISA helpers ==========================================
__device__ __forceinline__ uint32_t smem_u32(const void* p) {
    uint32_t a;
    asm("{ .reg .u64 t; cvta.to.shared.u64 t, %1; cvt.u32.u64 %0, t; }"
        : "=r"(a) : "l"(p));
    return a;
}
__device__ __forceinline__ void cp16(uint32_t sm, const void* g) {
    asm volatile("cp.async.cg.shared.global [%0], [%1], 16;" :: "r"(sm), "l"(g));
}
#define CP_COMMIT() asm volatile("cp.async.commit_group;" ::: "memory")
#define CP_WAIT(n)  asm volatile("cp.async.wait_group %0;" :: "n"(n) : "memory")

__device__ __forceinline__ void ldsm4(uint32_t* r, uint32_t addr) {
    asm volatile("ldmatrix.sync.aligned.m8n8.x4.shared.b16 {%0,%1,%2,%3}, [%4];"
                 : "=r"(r[0]), "=r"(r[1]), "=r"(r[2]), "=r"(r[3]) : "r"(addr));
}
__device__ __forceinline__ void mma16816(float* c, const uint32_t* a,
                                         uint32_t b0, uint32_t b1) {
    asm volatile("mma.sync.aligned.m16n8k16.row.col.f32.f16.f16.f32 "
                 "{%0,%1,%2,%3}, {%4,%5,%6,%7}, {%8,%9}, {%0,%1,%2,%3};"
                 : "+f"(c[0]), "+f"(c[1]), "+f"(c[2]), "+f"(c[3])
                 : "r"(a[0]), "r"(a[1]), "r"(a[2]), "r"(a[3]), "r"(b0), "r"(b1));
}

// ---------------- smem tiles: 128 rows x 64 fp16, padded 144B row stride -----
// 144 mod 128 = 16 -> 8 consecutive rows cover all 32 banks: LDSM conflict-free.
#define ROWB    144
#define TILE_B  (128 * ROWB)       // 18432
#define STAGE_B (3 * TILE_B)       // 55296 (A, Bh, Bl)
#define SMEM_DYN (2 * STAGE_B)     // 110592

__device__ __forceinline__ void cp_tile(uint32_t smtile,
                                        const __half* __restrict__ src,
                                        int tid) {
    #pragma unroll
    for (int i = 0; i < 4; i++) {
        int blk = tid + i * 256;          // 0..1023 : (row 0..127) x (8 x 16B)
        int r = blk >> 3, cb = blk & 7;
        cp16(smtile + (uint32_t)(r * ROWB + cb * 16),
             src + (size_t)r * CC + cb * 8);
    }
}

// ---------------- one K=64 chunk of MMAs (2 passes: A*Bh + A*Bl) -------------
// A 16x16 via ldmatrix.x4 (row = r0+((l>>3)&1)*8+(l&7), col = kk+(l>>4)*8);
// B x4 -> {b0(nt0), b0(nt1), b1(nt0), b1(nt1)}.
__device__ __forceinline__ void mma_chunk(uint32_t sA,
                                          uint32_t sBh, uint32_t sBl,
                                          int lane, int wm, int wn,
                                          float (&acc)[2][8][4]) {
    uint32_t loff = (uint32_t)((((lane >> 3) & 1) * 8 + (lane & 7)) * ROWB +
                               ((lane >> 4) * 8) * 2);
    #pragma unroll
    for (int kk = 0; kk < 64; kk += 16) {
        uint32_t kb = loff + (uint32_t)(kk * 2);
        uint32_t a[2][4], bh[4][4], bl[4][4];
        #pragma unroll
        for (int mt = 0; mt < 2; mt++)
            ldsm4(a[mt], sA + (uint32_t)((wm * 32 + mt * 16) * ROWB) + kb);
        #pragma unroll
        for (int np = 0; np < 4; np++) {
            uint32_t n0 = (uint32_t)((wn * 64 + np * 16) * ROWB) + kb;
            ldsm4(bh[np], sBh + n0);
            ldsm4(bl[np], sBl + n0);
        }
        #pragma unroll
        for (int mt = 0; mt < 2; mt++)
            #pragma unroll
            for (int np = 0; np < 4; np++) {
                mma16816(acc[mt][2 * np + 0], a[mt], bh[np][0], bh[np][2]);
                mma16816(acc[mt][2 * np + 1], a[mt], bh[np][1], bh[np][3]);
                mma16816(acc[mt][2 * np + 0], a[mt], bl[np][0], bl[np][2]);
                mma16816(acc[mt][2 * np + 1], a[mt], bl[np][1], bl[np][3]);
            }
    }
}

// ---------------- full K=1024 GEMM: double-buffered cp.async pipeline --------
__device__ __forceinline__ void gemm128(uint32_t smb,
                                        const __half* A,
                                        const __half* Bh, const __half* Bl,
                                        int tid, int lane, int wm, int wn,
                                        float (&acc)[2][8][4]) {
    const int NCH = 16;
    cp_tile(smb + 0 * TILE_B, A, tid);
    cp_tile(smb + 1 * TILE_B, Bh, tid);
    cp_tile(smb + 2 * TILE_B, Bl, tid);
    CP_COMMIT();
    for (int c = 0; c < NCH; c++) {
        uint32_t st = smb + (uint32_t)(c & 1) * STAGE_B;
        if (c + 1 < NCH) {
            uint32_t st2 = smb + (uint32_t)((c + 1) & 1) * STAGE_B;
            int co = (c + 1) * 64;
            cp_tile(st2 + 0 * TILE_B, A + co, tid);
            cp_tile(st2 + 1 * TILE_B, Bh + co, tid);
            cp_tile(st2 + 2 * TILE_B, Bl + co, tid);
            CP_COMMIT();
            CP_WAIT(1);
        } else {
            CP_WAIT(0);
        }
        __syncthreads();
        mma_chunk(st, st + TILE_B, st + 2 * TILE_B, lane, wm, wn, acc);
        __syncthreads();
    }
}

// ---------------- small prep kernels -----------------------------------------
__global__ void conv_x(const float* __restrict__ src) {
    int i = blockIdx.x * blockDim.x + threadIdx.x;
    G_XH[i] = __float2half_rn(src[i]);
}
__global__ void conv_w(const float* __restrict__ src) {
    int i = blockIdx.x * blockDim.x + threadIdx.x;
    float v = src[i];
    __half hb = __float2half_rn(v);
    G_WH[i] = hb;
    G_WL[i] = __float2half_rn(v - __half2float(hb));
}

// ---- two-stage folds: 64 blocks x 16-d slices -> partials -> reduce ---------
__global__ void fold_weff1(const float* __restrict__ W_proj,
                           const float* __restrict__ W_fc) {
    int b = blockIdx.x, t = threadIdx.x;
    #pragma unroll
    for (int cg = 0; cg < 4; cg++) {
        int c = cg * 256 + t;
        float s = 0.f;
        #pragma unroll
        for (int i = 0; i < 16; i++) {
            int d = b * 16 + i;
            s += W_fc[d] * W_proj[d * CC + c];
        }
        g_part[b * CC + c] = s;
    }
}
__global__ void fold_weff2() {
    int c = blockIdx.x * 256 + threadIdx.x;
    float s = 0.f;
    #pragma unroll
    for (int i = 0; i < 64; i++) s += g_part[i * CC + c];
    g_weff[c] = s;
}
__global__ void fold_u1(const float* __restrict__ W_attn) {
    const float* Wv = W_attn + (size_t)2 * CC * CC;
    int b = blockIdx.x, t = threadIdx.x;
    #pragma unroll
    for (int cg = 0; cg < 4; cg++) {
        int c = cg * 256 + t;
        float s = 0.f;
        #pragma unroll
        for (int i = 0; i < 16; i++) {
            int d = b * 16 + i;
            s += g_weff[d] * Wv[d * CC + c];
        }
        g_part[b * CC + c] = s;
    }
}
__global__ void fold_u2() {
    int c = blockIdx.x * 256 + threadIdx.x;
    float s = 0.f;
    #pragma unroll
    for (int i = 0; i < 64; i++) s += g_part[i * CC + c];
    g_u[c] = s;
}

__global__ void fold_scalars(const float* __restrict__ W_fc,
                             const float* __restrict__ b_proj,
                             const float* __restrict__ b_fc,
                             const float* __restrict__ b_attn) {
    __shared__ float s1[1024];
    __shared__ float s2[1024];
    int t = threadIdx.x;
    s1[t] = g_weff[t] * b_attn[2 * CC + t];
    s2[t] = W_fc[t] * b_proj[t];
    __syncthreads();
    for (int off = 512; off > 0; off >>= 1) {
        if (t < off) { s1[t] += s1[t + off]; s2[t] += s2[t + off]; }
        __syncthreads();
    }
    if (t == 0) { g_scal[0] = s1[0]; g_scal[1] = s2[0] + b_fc[0]; }
}

__global__ void vw_kernel(const float* __restrict__ x) {
    int warp = threadIdx.x >> 5, lane = threadIdx.x & 31;
    int row = blockIdx.x * 8 + warp;
    const float* xr = x + (size_t)row * CC;
    float s = 0.f;
    for (int c = lane; c < CC; c += 32) s += xr[c] * g_u[c];
    #pragma unroll
    for (int off = 16; off; off >>= 1) s += __shfl_xor_sync(0xffffffffu, s, off);
    if (lane == 0) g_vw[row] = s + g_scal[0];
}

// ================= q/k projection via HMMA ===================================
// grid (16, 128): C[16384, 2048] = xh @ (Wh+Wl)[0:2048]^T + bias
// q columns -> fp16 hi only; k columns -> fp16 hi + lo.
__global__ __launch_bounds__(256, 1)
void qk_mma(const float* __restrict__ bias) {
    extern __shared__ char smdyn[];
    __shared__ float s_bias[128];
    uint32_t smb = smem_u32(smdyn);
    int tid = threadIdx.x, lane = tid & 31, wid = tid >> 5;
    int wm = wid & 3, wn = wid >> 2;
    int bm = blockIdx.y * 128, bn = blockIdx.x * 128;

    if (tid < 128) s_bias[tid] = bias[bn + tid];

    float acc[2][8][4];
    #pragma unroll
    for (int mt = 0; mt < 2; mt++)
        #pragma unroll
        for (int nt = 0; nt < 8; nt++)
            #pragma unroll
            for (int e = 0; e < 4; e++) acc[mt][nt][e] = 0.f;

    gemm128(smb,
            G_XH + (size_t)bm * CC,
            G_WH + (size_t)bn * CC, G_WL + (size_t)bn * CC,
            tid, lane, wm, wn, acc);

    int g = lane >> 2, q = lane & 3;
    bool is_q = (bn < CC);
    int col0 = is_q ? bn : bn - CC;
    #pragma unroll
    for (int mt = 0; mt < 2; mt++)
        #pragma unroll
        for (int hf = 0; hf < 2; hf++) {
            int row = bm + wm * 32 + mt * 16 + hf * 8 + g;
            #pragma unroll
            for (int nt = 0; nt < 8; nt++) {
                int cl = wn * 64 + nt * 8 + q * 2;
                float v0 = acc[mt][nt][hf * 2 + 0] + s_bias[cl];
                float v1 = acc[mt][nt][hf * 2 + 1] + s_bias[cl + 1];
                __half h0 = __float2half_rn(v0);
                __half h1 = __float2half_rn(v1);
                uint32_t hp = ((uint32_t)*(uint16_t*)&h1 << 16) | *(uint16_t*)&h0;
                size_t off = (size_t)row * CC + col0 + cl;
                if (is_q) {
                    *reinterpret_cast<uint32_t*>(G_QH + off) = hp;
                } else {
                    __half l0 = __float2half_rn(v0 - __half2float(h0));
                    __half l1 = __float2half_rn(v1 - __half2float(h1));
                    uint32_t lp = ((uint32_t)*(uint16_t*)&l1 << 16) | *(uint16_t*)&l0;
                    *reinterpret_cast<uint32_t*>(G_KH + off) = hp;
                    *reinterpret_cast<uint32_t*>(G_KL + off) = lp;
                }
            }
        }
}

// ================= fused attention via HMMA ==================================
// grid (16, 8): CTA = (q-tile 128 rows, batch); loops 16 s-tiles of 128 keys.
__global__ __launch_bounds__(256, 1)
void attn_mma(float* __restrict__ out) {
    extern __shared__ char smdyn[];
    __shared__ float s_vw[128];
    __shared__ float s_m[2][128];
    __shared__ float s_l[2][128];
    __shared__ float s_o[2][128];
    uint32_t smb = smem_u32(smdyn);
    int tid = threadIdx.x, lane = tid & 31, wid = tid >> 5;
    int wm = wid & 3, wn = wid >> 2;
    int g = lane >> 2, q = lane & 3;
    int b = blockIdx.y, q0 = blockIdx.x * 128;
    const float SCALE = 0.03125f;  // 1024^-0.5

    const __half* A = G_QH + (size_t)(b * TT + q0) * CC;

    float m_w[4], l_w[4], o_w[4];
    #pragma unroll
    for (int s = 0; s < 4; s++) { m_w[s] = -1e30f; l_w[s] = 0.f; o_w[s] = 0.f; }

    for (int st = 0; st < 16; st++) {
        float acc[2][8][4];
        #pragma unroll
        for (int mt = 0; mt < 2; mt++)
            #pragma unroll
            for (int nt = 0; nt < 8; nt++)
                #pragma unroll
                for (int e = 0; e < 4; e++) acc[mt][nt][e] = 0.f;

        const __half* Bh = G_KH + (size_t)(b * TT + st * 128) * CC;
        const __half* Bl = G_KL + (size_t)(b * TT + st * 128) * CC;
        gemm128(smb, A, Bh, Bl, tid, lane, wm, wn, acc);

        if (tid < 128) s_vw[tid] = g_vw[b * TT + st * 128 + tid];
        __syncthreads();

        #pragma unroll
        for (int mt = 0; mt < 2; mt++)
            #pragma unroll
            for (int hf = 0; hf < 2; hf++) {
                int slot = mt * 2 + hf;
                float mx = -1e30f;
                #pragma unroll
                for (int nt = 0; nt < 8; nt++) {
                    mx = fmaxf(mx, acc[mt][nt][hf * 2 + 0]);
                    mx = fmaxf(mx, acc[mt][nt][hf * 2 + 1]);
                }
                mx = fmaxf(mx, __shfl_xor_sync(0xffffffffu, mx, 1));
                mx = fmaxf(mx, __shfl_xor_sync(0xffffffffu, mx, 2));
                float mn = fmaxf(m_w[slot], mx * SCALE);
                float corr = __expf(m_w[slot] - mn);
                float ps = 0.f, os = 0.f;
                #pragma unroll
                for (int nt = 0; nt < 8; nt++) {
                    int cl = wn * 64 + nt * 8 + q * 2;
                    float p0 = __expf(acc[mt][nt][hf * 2 + 0] * SCALE - mn);
                    float p1 = __expf(acc[mt][nt][hf * 2 + 1] * SCALE - mn);
                    ps += p0 + p1;
                    os += p0 * s_vw[cl] + p1 * s_vw[cl + 1];
                }
                ps += __shfl_xor_sync(0xffffffffu, ps, 1);
                ps += __shfl_xor_sync(0xffffffffu, ps, 2);
                os += __shfl_xor_sync(0xffffffffu, os, 1);
                os += __shfl_xor_sync(0xffffffffu, os, 2);
                l_w[slot] = l_w[slot] * corr + ps;
                o_w[slot] = o_w[slot] * corr + os;
                m_w[slot] = mn;
            }
        __syncthreads();   // s_vw reuse next tile
    }

    if (q == 0) {
        #pragma unroll
        for (int mt = 0; mt < 2; mt++)
            #pragma unroll
            for (int hf = 0; hf < 2; hf++) {
                int slot = mt * 2 + hf;
                int rl = wm * 32 + mt * 16 + hf * 8 + g;
                s_m[wn][rl] = m_w[slot];
                s_l[wn][rl] = l_w[slot];
                s_o[wn][rl] = o_w[slot];
            }
    }
    __syncthreads();
    if (wn == 0 && q == 0) {
        float co = g_scal[1];
        #pragma unroll
        for (int mt = 0; mt < 2; mt++)
            #pragma unroll
            for (int hf = 0; hf < 2; hf++) {
                int rl = wm * 32 + mt * 16 + hf * 8 + g;
                float m0 = s_m[0][rl], m1 = s_m[1][rl];
                float mM = fmaxf(m0, m1);
                float e0 = __expf(m0 - mM), e1 = __expf(m1 - mM);
                float lsum = s_l[0][rl] * e0 + s_l[1][rl] * e1;
                float osum = s_o[0][rl] * e0 + s_o[1][rl] * e1;
                out[b * TT + q0 + rl] = osum / lsum + co;
            }
    }
}

// ---------------- launch ------------------------------------------------------
extern "C" void kernel_launch(void* const* d_in, const int* in_sizes, int n_in,
                              void* d_out, int out_size) {
    const float* x      = (const float*)d_in[0];
    const float* W_attn = (const float*)d_in[1];
    const float* b_attn = (const float*)d_in[2];
    const float* W_proj = (const float*)d_in[3];
    const float* b_proj = (const float*)d_in[4];
    const float* W_fc   = (const float*)d_in[5];
    const float* b_fc   = (const float*)d_in[6];
    float* out = (float*)d_out;

    cudaFuncSetAttribute(qk_mma,   cudaFuncAttributeMaxDynamicSharedMemorySize, SMEM_DYN);
    cudaFuncSetAttribute(attn_mma, cudaFuncAttributeMaxDynamicSharedMemorySize, SMEM_DYN);

    int nx = MM * CC;       // divisible by 256
    int nw = 2 * CC * CC;   // divisible by 256
    conv_x<<<nx / 256, 256>>>(x);
    conv_w<<<nw / 256, 256>>>(W_attn);
    fold_weff1<<<64, 256>>>(W_proj, W_fc);
    fold_weff2<<<4, 256>>>();
    fold_u1<<<64, 256>>>(W_attn);
    fold_u2<<<4, 256>>>();
    fold_scalars<<<1, 1024>>>(W_fc, b_proj, b_fc, b_attn);
    vw_kernel<<<MM / 8, 256>>>(x);

    qk_mma<<<dim3(16, 128), 256, SMEM_DYN>>>(b_attn);
    attn_mma<<<dim3(16, 8), 256, SMEM_DYN>>>(out);
}